// round 17
// baseline (speedup 1.0000x reference)
#include <cuda_runtime.h>
#include <cstdint>

static constexpr int MAX_E = 1600000;             // < 2^21 (ids fit 21 bits)
static constexpr int NROWS = 65536;               // row ids < 2^16
static constexpr int CAP   = 128;                 // slots per row bucket
static constexpr int ROWS_PER_BLK = 16;
static constexpr int NBLK_D = NROWS / ROWS_PER_BLK;  // 4096
static constexpr int CHUNK = 256;                 // arrwp rows per pipeline stage
static constexpr int FUSED_GRID = 296;            // 148 SMs x 2 blocks

// Scratch (allocation-free: __device__ globals; zero-initialized at load,
// and each launch leaves them zeroed again -> graph replays start clean)
__device__ unsigned long long g_bucket[(size_t)NROWS * CAP];  // (col<<32)|orig
__device__ int g_cnt[NROWS];
__device__ uint32_t g_segflag[MAX_E];             // per ORIGINAL edge: (seg<<1)|leader
__device__ unsigned long long g_desc[NBLK_D];     // lookback: (value<<2)|state
__device__ unsigned long long g_duplist[MAX_E];   // (seg<<21)|orig for duplicates
__device__ int g_dupcnt;
__device__ int g_blkctr;
__device__ int g_nu;

// ---------------------------------------------------------------------------
__device__ __forceinline__ uint32_t smem_u32(const void* p) {
    uint32_t a;
    asm("{ .reg .u64 t; cvta.to.shared.u64 t, %1; cvt.u32.u64 %0, t; }"
        : "=r"(a) : "l"(p));
    return a;
}
__device__ __forceinline__ void fma2(unsigned long long& acc,
                                     unsigned long long a, unsigned long long b) {
    asm("fma.rn.f32x2 %0, %1, %2, %0;" : "+l"(acc) : "l"(a), "l"(b));
}
__device__ __forceinline__ float hsum2(unsigned long long a) {
    float x, y;
    asm("mov.b64 {%0, %1}, %2;" : "=f"(x), "=f"(y) : "l"(a));
    return x + y;
}
__device__ __forceinline__ void mbar_init(uint32_t mbar, uint32_t cnt) {
    asm volatile("mbarrier.init.shared.b64 [%0], %1;" :: "r"(mbar), "r"(cnt) : "memory");
}
__device__ __forceinline__ void mbar_expect_tx(uint32_t mbar, uint32_t bytes) {
    asm volatile("mbarrier.arrive.expect_tx.shared.b64 _, [%0], %1;"
                 :: "r"(mbar), "r"(bytes) : "memory");
}
__device__ __forceinline__ void mbar_wait(uint32_t mbar, uint32_t parity) {
    uint32_t done;
    asm volatile(
        "{ .reg .pred p; mbarrier.try_wait.parity.acquire.cta.shared::cta.b64 p, [%1], %2;"
        " selp.b32 %0, 1, 0, p; }"
        : "=r"(done) : "r"(mbar), "r"(parity) : "memory");
    if (!done) {
        asm volatile(
            "{ .reg .pred P1; WL%=:"
            " mbarrier.try_wait.parity.acquire.cta.shared::cta.b64 P1, [%0], %1, 0x989680;"
            " @P1 bra.uni WD%=; bra.uni WL%=; WD%=: }"
            :: "r"(mbar), "r"(parity) : "memory");
    }
}
__device__ __forceinline__ void bulk_copy(uint32_t dst, const void* src,
                                          uint32_t bytes, uint32_t mbar) {
    asm volatile(
        "cp.async.bulk.shared::cta.global.mbarrier::complete_tx::bytes [%0], [%1], %2, [%3];"
        :: "r"(dst), "l"(src), "r"(bytes), "r"(mbar) : "memory");
}

// ---------------------------------------------------------------------------
// 1. bucket scatter: g_bucket[row*CAP + slot] = (col<<32)|orig
__global__ void k_bucket(const int* __restrict__ ei, const int* __restrict__ ai,
                         int Ee, int Ea) {
    int E = Ee + Ea;
    int i = blockIdx.x * blockDim.x + threadIdx.x;
    if (i >= E) return;
    int row, col;
    if (i < Ee) { row = ei[i];          col = ei[Ee + i]; }
    else        { int j = i - Ee; row = ai[j]; col = ai[Ea + j]; }
    int slot = atomicAdd(&g_cnt[row], 1);
    if (slot < CAP)
        g_bucket[(size_t)row * CAP + slot] =
            ((unsigned long long)(uint32_t)col << 32) | (unsigned long long)i;
}

// --- per-row machinery: u32 bitonic (size-adapted), flags, ranks ------------
template <int R>
__device__ __forceinline__ int row_phase1(const unsigned long long* __restrict__ eb,
                                          int n, int lane,
                                          uint32_t v[4], uint32_t og[4],
                                          int rk[4], int fl[4]) {
    const unsigned FULL = 0xFFFFFFFFu;
    #pragma unroll
    for (int k = 0; k < R; k++) {
        int p = k * 32 + lane;
        if (p < n) {
            unsigned long long e = eb[p];
            og[k] = (uint32_t)e;
            v[k]  = ((uint32_t)(e >> 32) << 8) | (uint32_t)p;  // (col<<8)|slot
        } else {
            og[k] = 0u;
            v[k]  = 0xFFFFFFFFu;
        }
    }
    #pragma unroll
    for (int s = 2; s <= 32 * R; s <<= 1) {
        #pragma unroll
        for (int d = (32 * R) >> 1; d >= 1; d >>= 1) {
            if (d >= s) continue;
            if (d >= 32) {
                int dd = d >> 5;
                #pragma unroll
                for (int k = 0; k < R; k++) {
                    if ((k & dd) == 0) {
                        int kh = k | dd;
                        bool up = (((k * 32 + lane) & s) == 0);
                        if ((v[k] > v[kh]) == up) { uint32_t t = v[k]; v[k] = v[kh]; v[kh] = t; }
                    }
                }
            } else {
                #pragma unroll
                for (int k = 0; k < R; k++) {
                    int p = k * 32 + lane;
                    bool up = ((p & s) == 0);
                    uint32_t o = __shfl_xor_sync(FULL, v[k], d);
                    bool lower = ((lane & d) == 0);
                    uint32_t mn = v[k] < o ? v[k] : o;
                    uint32_t mx = v[k] < o ? o : v[k];
                    v[k] = (up == lower) ? mn : mx;
                }
            }
        }
    }
    int carry = 0;
    #pragma unroll
    for (int k = 0; k < R; k++) {
        int p = k * 32 + lane;
        uint32_t pv = __shfl_up_sync(FULL, v[k], 1);
        uint32_t wrap = (k > 0) ? __shfl_sync(FULL, v[(k > 0) ? k - 1 : 0], 31)
                                : 0xFFFFFFFFu;
        if (lane == 0) pv = wrap;
        int f = 0;
        if (p < n) f = (p == 0) ? 1 : ((v[k] >> 8) != (pv >> 8));
        unsigned bal = __ballot_sync(FULL, f);
        rk[k] = carry + __popc(bal & (0xFFFFFFFFu >> (31 - lane)));
        fl[k] = f;
        carry += __popc(bal);
    }
    return carry;
}

// phase 2: scatter segflag[orig]; leaders also write out_r/out_c (seg-contig,
// streaming); non-leaders append to the duplicate worklist.
template <int R>
__device__ __forceinline__ void row_phase2(int n, int lane, int rowbase, int row,
                                           float* __restrict__ out, int E,
                                           const uint32_t v[4], const uint32_t og[4],
                                           const int rk[4], const int fl[4]) {
    const unsigned FULL = 0xFFFFFFFFu;
    #pragma unroll
    for (int k = 0; k < R; k++) {
        int p = k * 32 + lane;
        uint32_t slot = v[k] & 0xFFu;
        uint32_t o0 = __shfl_sync(FULL, og[0], slot & 31);
        uint32_t o1 = (R > 1) ? __shfl_sync(FULL, og[1], slot & 31) : 0u;
        uint32_t o2 = (R > 2) ? __shfl_sync(FULL, og[2], slot & 31) : 0u;
        uint32_t o3 = (R > 3) ? __shfl_sync(FULL, og[3], slot & 31) : 0u;
        uint32_t r5 = slot >> 5;
        uint32_t orig = (r5 == 0) ? o0 : (r5 == 1) ? o1 : (r5 == 2) ? o2 : o3;
        if (p < n) {
            int seg = rowbase + rk[k] - 1;
            g_segflag[orig] = ((uint32_t)seg << 1) | (uint32_t)fl[k];
            if (fl[k]) {
                out[seg]     = (float)row;
                out[E + seg] = (float)(v[k] >> 8);
            } else {
                int di = atomicAdd(&g_dupcnt, 1);
                g_duplist[di] = ((unsigned long long)(uint32_t)seg << 21)
                              | (unsigned long long)orig;
            }
        }
    }
}

// 2. 16 rows per 512-thread block; warp-per-row; warp-parallel lookback.
__global__ void __launch_bounds__(512)
k_rowsort(float* __restrict__ out, int E) {
    const unsigned FULL = 0xFFFFFFFFu;
    __shared__ int s_bid;
    __shared__ int s_u[ROWS_PER_BLK];
    __shared__ int s_uex[ROWS_PER_BLK];
    __shared__ int s_excl;
    int tid = threadIdx.x, lane = tid & 31, wid = tid >> 5;
    if (tid == 0) s_bid = atomicAdd(&g_blkctr, 1);
    __syncthreads();
    const int bid = s_bid;
    const int row = bid * ROWS_PER_BLK + wid;
    int n = min(g_cnt[row], CAP);
    const unsigned long long* eb = g_bucket + (size_t)row * CAP;

    uint32_t v[4], og[4];
    int rk[4], fl[4];
    int u = 0;
    int mode = (n == 0) ? -1 : (n <= 64) ? 0 : 1;
    if (mode == 0)      u = row_phase1<2>(eb, n, lane, v, og, rk, fl);
    else if (mode == 1) u = row_phase1<4>(eb, n, lane, v, og, rk, fl);

    if (lane == 0) s_u[wid] = u;
    __syncthreads();

    if (wid == 0) {
        int val  = (lane < ROWS_PER_BLK) ? s_u[lane] : 0;
        int incl = val;
        #pragma unroll
        for (int d = 1; d < ROWS_PER_BLK; d <<= 1) {
            int nb = __shfl_up_sync(FULL, incl, d);
            if (lane >= d) incl += nb;
        }
        if (lane < ROWS_PER_BLK) s_uex[lane] = incl - val;
        int agg = __shfl_sync(FULL, incl, ROWS_PER_BLK - 1);

        int excl = 0;
        if (bid == 0) {
            if (lane == 0)
                atomicExch(&g_desc[0], (((unsigned long long)agg) << 2) | 2ull);
        } else {
            if (lane == 0)
                atomicExch(&g_desc[bid], (((unsigned long long)agg) << 2) | 1ull);
            __syncwarp();
            int jtop = bid - 1;
            while (true) {
                int idx = jtop - lane;
                unsigned long long d; unsigned st;
                if (idx >= 0) { d = atomicAdd(&g_desc[idx], 0ull); st = (unsigned)(d & 3ull); }
                else          { d = 2ull; st = 2u; }      // virtual prefix 0
                unsigned pref = __ballot_sync(FULL, st == 2u);
                unsigned nrdy = __ballot_sync(FULL, st == 0u);
                if (pref) {
                    int lp = __ffs(pref) - 1;
                    if ((nrdy & ((lp ? ((1u << lp) - 1u) : 0u))) == 0) {
                        int contrib = (lane <= lp) ? (int)(d >> 2) : 0;
                        #pragma unroll
                        for (int o = 16; o; o >>= 1)
                            contrib += __shfl_down_sync(FULL, contrib, o);
                        excl += __shfl_sync(FULL, contrib, 0);
                        break;
                    }
                } else if (!nrdy) {
                    int contrib = (int)(d >> 2);
                    #pragma unroll
                    for (int o = 16; o; o >>= 1)
                        contrib += __shfl_down_sync(FULL, contrib, o);
                    excl += __shfl_sync(FULL, contrib, 0);
                    jtop -= 32;
                    continue;
                }
                __nanosleep(20);
            }
            if (lane == 0)
                atomicExch(&g_desc[bid],
                           (((unsigned long long)(excl + agg)) << 2) | 2ull);
        }
        if (lane == 0) {
            s_excl = excl;
            if (bid == NBLK_D - 1) g_nu = excl + agg;
        }
    }
    __syncthreads();
    const int rowbase = s_excl + s_uex[wid];

    if (mode == 0)      row_phase2<2>(n, lane, rowbase, row, out, E, v, og, rk, fl);
    else if (mode == 1) row_phase2<4>(n, lane, rowbase, row, out, E, v, og, rk, fl);
}

// 3. fused: arrwp projection pipeline + raw-edge copy, with BLOCK-PARITY
//    ordering (even: A then B; odd: B then A) so DRAM streaming overlaps
//    compute across co-resident blocks. Tail section also resets scratch.
static constexpr int SM_FLAG = 16;
static constexpr int SM_ATTR = 4096;              // flags fit below
static constexpr int SM_TOTAL = SM_ATTR + 2 * CHUNK * 128;  // 69632

__global__ void __launch_bounds__(256, 2)
k_fused(const float* __restrict__ eattr, const float* __restrict__ aattr,
        const float* __restrict__ W, float* __restrict__ out,
        int Ee, int Ea) {
    extern __shared__ unsigned char sm[];
    const uint32_t sbase = smem_u32(sm);
    const int E = Ee + Ea;
    float* out_attr = out + 2 * (size_t)E;

    const int tid  = threadIdx.x;
    const int lane = tid & 31;
    const int wrp  = tid >> 5;        // 0..7: each warp owns 32 edges per chunk

    // per-lane W: rows 2*lane and 2*lane+1, as packed f32x2 over k-pairs
    unsigned long long wa[16], wb[16];
    {
        const unsigned long long* Wa =
            reinterpret_cast<const unsigned long long*>(W + (2 * lane) * 32);
        const unsigned long long* Wb =
            reinterpret_cast<const unsigned long long*>(W + (2 * lane + 1) * 32);
        #pragma unroll
        for (int q = 0; q < 16; q++) { wa[q] = __ldg(Wa + q); wb[q] = __ldg(Wb + q); }
    }

    const int nChunks = (Ea + CHUNK - 1) / CHUNK;
    if (tid == 0) { mbar_init(sbase + 0, 1); mbar_init(sbase + 8, 1); }
    __syncthreads();

    auto issue = [&](int c, int s) {
        int base = c * CHUNK;
        int rem  = min(CHUNK, Ea - base);
        uint32_t attrB = (uint32_t)rem * 128u;
        uint32_t flagB = ((uint32_t)rem * 4u + 15u) & ~15u;
        uint32_t mb = sbase + s * 8;
        mbar_expect_tx(mb, attrB + flagB);
        bulk_copy(sbase + SM_ATTR + s * (CHUNK * 128), aattr + (size_t)base * 32, attrB, mb);
        bulk_copy(sbase + SM_FLAG + s * (CHUNK * 4), &g_segflag[Ee + base], flagB, mb);
    };

    // ---- section A: arrwp projection (double-buffered bulk-async pipeline)
    auto sectionA = [&]() {
        int c0 = blockIdx.x;
        if (c0 >= nChunks) return;
        if (tid == 0) issue(c0, 0);
        int phase0 = 0, phase1 = 0;
        int li = 0;
        for (int c = c0; c < nChunks; c += gridDim.x, li++) {
            int s = li & 1;
            int cn = c + gridDim.x;
            if (tid == 0 && cn < nChunks) issue(cn, s ^ 1);

            mbar_wait(sbase + s * 8, s ? phase1 : phase0);
            if (s) phase1 ^= 1; else phase0 ^= 1;

            int rem  = min(CHUNK, Ea - c * CHUNK);
            int lbase = wrp * 32;                  // 32 edges per warp
            if (lbase < rem) {
                int cnt = min(32, rem - lbase);
                const uint32_t* flag_s = (const uint32_t*)(sm + SM_FLAG + s * (CHUNK * 4));
                const float* attr_s = (const float*)(sm + SM_ATTR + s * (CHUNK * 128));

                int cnt2 = cnt & ~1;
                for (int t = 0; t < cnt2; t += 2) {
                    uint2 ff = *reinterpret_cast<const uint2*>(flag_s + lbase + t);
                    const ulonglong2* A0 =
                        (const ulonglong2*)(attr_s + (lbase + t) * 32);
                    const ulonglong2* A1 =
                        (const ulonglong2*)(attr_s + (lbase + t + 1) * 32);
                    unsigned long long e0a = 0ull, e0b = 0ull;
                    unsigned long long e1a = 0ull, e1b = 0ull;
                    #pragma unroll
                    for (int q = 0; q < 8; q++) {
                        ulonglong2 p0 = A0[q];           // uniform LDS.128
                        ulonglong2 p1 = A1[q];
                        fma2(e0a, p0.x, wa[2 * q]);
                        fma2(e0a, p0.y, wa[2 * q + 1]);
                        fma2(e0b, p0.x, wb[2 * q]);
                        fma2(e0b, p0.y, wb[2 * q + 1]);
                        fma2(e1a, p1.x, wa[2 * q]);
                        fma2(e1a, p1.y, wa[2 * q + 1]);
                        fma2(e1b, p1.x, wb[2 * q]);
                        fma2(e1b, p1.y, wb[2 * q + 1]);
                    }
                    if (ff.x & 1u) {
                        float2 v; v.x = hsum2(e0a); v.y = hsum2(e0b);
                        reinterpret_cast<float2*>(
                            out_attr + (size_t)(ff.x >> 1) * 64)[lane] = v;
                    }
                    if (ff.y & 1u) {
                        float2 v; v.x = hsum2(e1a); v.y = hsum2(e1b);
                        reinterpret_cast<float2*>(
                            out_attr + (size_t)(ff.y >> 1) * 64)[lane] = v;
                    }
                }
                if (cnt & 1) {
                    int t = cnt2;
                    uint32_t sfe = flag_s[lbase + t];
                    if (sfe & 1u) {
                        const ulonglong2* A0 =
                            (const ulonglong2*)(attr_s + (lbase + t) * 32);
                        unsigned long long e0a = 0ull, e0b = 0ull;
                        #pragma unroll
                        for (int q = 0; q < 8; q++) {
                            ulonglong2 p0 = A0[q];
                            fma2(e0a, p0.x, wa[2 * q]);
                            fma2(e0a, p0.y, wa[2 * q + 1]);
                            fma2(e0b, p0.x, wb[2 * q]);
                            fma2(e0b, p0.y, wb[2 * q + 1]);
                        }
                        float2 v; v.x = hsum2(e0a); v.y = hsum2(e0b);
                        reinterpret_cast<float2*>(
                            out_attr + (size_t)(sfe >> 1) * 64)[lane] = v;
                    }
                }
            }
            __syncthreads();
        }
    };

    // ---- section B: raw-edge attr copy (grid-stride, 2 float4 per thread)
    auto sectionB = [&]() {
        const int gtid   = blockIdx.x * blockDim.x + tid;
        const int stride = gridDim.x * blockDim.x;
        const float4* eattr4 = reinterpret_cast<const float4*>(eattr);
        float4* out_attr4 = reinterpret_cast<float4*>(out_attr);
        const int total = Ee * 8;                  // 8 x 32B per edge
        for (int i = gtid; i < total; i += stride) {
            int e = i >> 3, h = (i & 7) * 2;
            uint32_t sf = g_segflag[e];
            if (!(sf & 1u)) continue;
            int seg = (int)(sf >> 1);
            float4 v0 = eattr4[(size_t)e * 16 + h];
            float4 v1 = eattr4[(size_t)e * 16 + h + 1];
            out_attr4[(size_t)seg * 16 + h]     = v0;
            out_attr4[(size_t)seg * 16 + h + 1] = v1;
        }
    };

    if (blockIdx.x & 1) { sectionB(); sectionA(); }
    else                { sectionA(); sectionB(); }

    // ---- section C: tail pad [nu, E) + scratch reset for next graph replay
    {
        const int nu = g_nu;
        const int gtid   = blockIdx.x * blockDim.x + tid;
        const int stride = gridDim.x * blockDim.x;
        for (int i = nu + gtid; i < E; i += stride) {
            out[i]     = -1.0f;
            out[E + i] = -1.0f;
        }
        size_t start = (size_t)nu * 64;
        size_t end   = (size_t)E * 64;
        for (size_t i = start + gtid; i < end; i += (size_t)stride)
            out_attr[i] = 0.0f;
        if (gtid == 0)
            out[2 * (size_t)E + (size_t)E * 64] = (float)nu;
        // reset scratch consumed by k_bucket / k_rowsort (already done this run)
        for (int i = gtid; i < NROWS; i += stride) g_cnt[i] = 0;
        for (int i = gtid; i < NBLK_D; i += stride) g_desc[i] = 0ull;
        if (gtid == 0) g_blkctr = 0;
    }
}

// 4. duplicate scatter: worklist-driven (~hundreds of entries); SINGLE block
//    so g_dupcnt can be read by all threads before being reset at the end.
__global__ void __launch_bounds__(1024)
k_scatter_dups(const float* __restrict__ eattr,
               const float* __restrict__ aattr,
               const float* __restrict__ W,
               float* __restrict__ out, int Ee, int Ea) {
    int E = Ee + Ea;
    int ndup = g_dupcnt;
    for (int i = threadIdx.x; i < ndup; i += blockDim.x) {
        unsigned long long ent = g_duplist[i];
        int seg  = (int)(ent >> 21);
        int orig = (int)(ent & 0x1FFFFFull);
        float* orow = out + 2 * (size_t)E + (size_t)seg * 64;
        if (orig < Ee) {
            const float* a = eattr + (size_t)orig * 64;
            for (int j = 0; j < 64; j++) atomicAdd(orow + j, a[j]);
        } else {
            const float* a = aattr + (size_t)(orig - Ee) * 32;
            float av[32];
            #pragma unroll
            for (int k = 0; k < 32; k++) av[k] = a[k];
            for (int j = 0; j < 64; j++) {
                float s = 0.f;
                #pragma unroll
                for (int k = 0; k < 32; k++) s += av[k] * W[j * 32 + k];
                atomicAdd(orow + j, s);
            }
        }
    }
    __syncthreads();
    if (threadIdx.x == 0) g_dupcnt = 0;
}

// ---------------------------------------------------------------------------
extern "C" void kernel_launch(void* const* d_in, const int* in_sizes, int n_in,
                              void* d_out, int out_size) {
    (void)n_in; (void)out_size;
    const int*   ei    = (const int*)d_in[0];
    const float* eattr = (const float*)d_in[1];
    const int*   ai    = (const int*)d_in[2];
    const float* aattr = (const float*)d_in[3];
    const float* W     = (const float*)d_in[4];
    const int Ee = in_sizes[0] / 2;
    const int Ea = in_sizes[2] / 2;
    const int E  = Ee + Ea;
    float* out = (float*)d_out;

    static bool attr_set = false;
    if (!attr_set) {
        cudaFuncSetAttribute(k_fused,
                             cudaFuncAttributeMaxDynamicSharedMemorySize, SM_TOTAL);
        attr_set = true;
    }

    const int T = 256;
    k_bucket<<<(E + T - 1) / T, T>>>(ei, ai, Ee, Ea);
    k_rowsort<<<NBLK_D, 512>>>(out, E);
    k_fused<<<FUSED_GRID, T, SM_TOTAL>>>(eattr, aattr, W, out, Ee, Ea);
    k_scatter_dups<<<1, 1024>>>(eattr, aattr, W, out, Ee, Ea);
}